// round 4
// baseline (speedup 1.0000x reference)
#include <cuda_runtime.h>
#include <math.h>

// ---- problem dims ----
#define B_   64
#define S_   200
#define T_   32
#define V_   50000
#define E_   128
#define C_   128
#define H_   100
#define OUT_ 104
#define NT_  (B_*S_)  // 12800 trees
#define N_   (NT_*T_) // 409600 nodes

// ---- packed f32x2 helpers (Blackwell FFMA2 path) ----
typedef unsigned long long u64;

#define FMA2(d, a, b, c) \
    asm("fma.rn.f32x2 %0, %1, %2, %3;" : "=l"(d) : "l"(a), "l"(b), "l"(c))
#define ADD2(d, a, b) \
    asm("add.rn.f32x2 %0, %1, %2;" : "=l"(d) : "l"(a), "l"(b))

__device__ __forceinline__ u64 dup2(float x) {
    u64 r;
    asm("mov.b64 %0, {%1, %1};" : "=l"(r) : "r"(__float_as_uint(x)));
    return r;
}
__device__ __forceinline__ float2 unpack2(u64 v) {
    unsigned lo, hi;
    asm("mov.b64 {%0, %1}, %2;" : "=r"(lo), "=r"(hi) : "l"(v));
    return make_float2(__uint_as_float(lo), __uint_as_float(hi));
}
// fast tanh via EX2/RCP MUFUs (accuracy ~1e-6, saturates correctly at +/-1)
__device__ __forceinline__ float tanh_fast(float x) {
    return 1.0f - 2.0f * __frcp_rn(__expf(2.0f * x) + 1.0f);
}

// ---- device scratch (no allocations allowed) ----
__device__ float g_ctable[V_ * C_];      // 25.6 MB : W*emb(v)+b per vocab entry
__device__ float g_treevec[NT_ * C_];    // 6.55 MB : per-tree max-pooled hidden
__device__ float g_gx[NT_ * 600];        // 30.7 MB : [s*64+b][600] input gates (f|b)
__device__ float g_poolT[200 * 64];      // [2H][B] : transposed time-max pool

// ============================================================================
// GEMM (NT): C[m,n] = sum_k A[m,k]*B[n,k] + bias[n].  K fixed at 128.
// BM=128, BN=64, BK=32, 256 threads, 8m x 4n per thread, f32x2-packed along m.
// ============================================================================
__global__ void __launch_bounds__(256) gemm_nt_kernel(
    const float* __restrict__ A_in,
    const float* __restrict__ B1, const float* __restrict__ B2, int nsplit,
    int Ncols,
    const float* __restrict__ bias1, const float* __restrict__ bias2,
    int M, int mode)
{
    __shared__ __align__(16) float As[32][132];   // k-major, 128 m cols
    __shared__ __align__(16) float Bs[32][68];    // k-major, 64 n cols

    const float* __restrict__ A = (mode == 0) ? A_in : g_treevec;

    const int m0 = blockIdx.y * 128;
    const int n0 = blockIdx.x * 64;
    const int tid = threadIdx.x;
    const int tx = tid & 15;       // n: 4 per thread
    const int ty = tid >> 4;       // m: 8 per thread

    u64 acc[4][4];                 // [m-pair][n]
    #pragma unroll
    for (int i = 0; i < 4; i++)
        #pragma unroll
        for (int j = 0; j < 4; j++) acc[i][j] = 0ull;

    for (int k0 = 0; k0 < 128; k0 += 32) {
        #pragma unroll
        for (int i = 0; i < 4; i++) {
            int f   = tid + i * 256;   // 0..1023 float4 slots
            int row = f >> 3;          // 0..127
            int kq  = f & 7;
            float4 v = make_float4(0.f, 0.f, 0.f, 0.f);
            int m = m0 + row;
            if (m < M) v = *(const float4*)(A + (size_t)m * 128 + k0 + kq * 4);
            As[kq*4+0][row] = v.x; As[kq*4+1][row] = v.y;
            As[kq*4+2][row] = v.z; As[kq*4+3][row] = v.w;
        }
        #pragma unroll
        for (int i = 0; i < 2; i++) {
            int f   = tid + i * 256;
            int row = f >> 3;          // 0..63
            int kq  = f & 7;
            float4 v = make_float4(0.f, 0.f, 0.f, 0.f);
            int n = n0 + row;
            if (n < Ncols) {
                const float* Bp = (n < nsplit) ? (B1 + (size_t)n * 128)
                                               : (B2 + (size_t)(n - nsplit) * 128);
                v = *(const float4*)(Bp + k0 + kq * 4);
            }
            Bs[kq*4+0][row] = v.x; Bs[kq*4+1][row] = v.y;
            Bs[kq*4+2][row] = v.z; Bs[kq*4+3][row] = v.w;
        }
        __syncthreads();

        #pragma unroll
        for (int kk = 0; kk < 32; kk++) {
            ulonglong2 ap0 = *(const ulonglong2*)&As[kk][ty * 8];
            ulonglong2 ap1 = *(const ulonglong2*)&As[kk][ty * 8 + 4];
            float4 bv = *(const float4*)&Bs[kk][tx * 4];
            u64 bd[4] = { dup2(bv.x), dup2(bv.y), dup2(bv.z), dup2(bv.w) };
            u64 ap[4] = { ap0.x, ap0.y, ap1.x, ap1.y };
            #pragma unroll
            for (int mp = 0; mp < 4; mp++)
                #pragma unroll
                for (int jj = 0; jj < 4; jj++)
                    FMA2(acc[mp][jj], ap[mp], bd[jj], acc[mp][jj]);
        }
        __syncthreads();
    }

    int nbase = n0 + tx * 4;
    bool nok = (nbase < Ncols);
    float4 bias4 = make_float4(0.f, 0.f, 0.f, 0.f);
    if (nok) {
        const float* bp = (nbase < nsplit) ? (bias1 + nbase)
                                           : (bias2 + (nbase - nsplit));
        bias4 = make_float4(bp[0], bp[1], bp[2], bp[3]);
    }
    #pragma unroll
    for (int mp = 0; mp < 4; mp++) {
        float2 c0 = unpack2(acc[mp][0]);
        float2 c1 = unpack2(acc[mp][1]);
        float2 c2 = unpack2(acc[mp][2]);
        float2 c3 = unpack2(acc[mp][3]);
        float4 rlo = make_float4(c0.x + bias4.x, c1.x + bias4.y,
                                 c2.x + bias4.z, c3.x + bias4.w);
        float4 rhi = make_float4(c0.y + bias4.x, c1.y + bias4.y,
                                 c2.y + bias4.z, c3.y + bias4.w);
        int m = m0 + ty * 8 + 2 * mp;
        #pragma unroll
        for (int half = 0; half < 2; half++) {
            int mm = m + half;
            if (mm >= M || !nok) continue;
            float4 r = half ? rhi : rlo;
            if (mode == 0) {
                *(float4*)(g_ctable + (size_t)mm * 128 + nbase) = r;
            } else {
                int s = mm % 200;     // tree mm = b*200 + s
                int b = mm / 200;
                *(float4*)(g_gx + (size_t)(s * 64 + b) * 600 + nbase) = r;
            }
        }
    }
}

// ============================================================================
// Tree encode: gather + fixed-topology subtree sums + max pool.
// ============================================================================
__global__ void __launch_bounds__(128) tree_kernel(const int* __restrict__ tokens)
{
    const int tree = blockIdx.x;
    const int c = threadIdx.x;
    __shared__ int tok[32];
    if (c < 32) tok[c] = tokens[tree * 32 + c];
    __syncthreads();

    float v[32];
    #pragma unroll
    for (int i = 0; i < 32; i++)
        v[i] = g_ctable[(size_t)tok[i] * 128 + c];

    #pragma unroll
    for (int i = 31; i >= 1; i--)
        v[(i - 1) >> 1] += v[i];

    float m = v[0];
    #pragma unroll
    for (int i = 1; i < 32; i++) m = fmaxf(m, v[i]);

    g_treevec[(size_t)tree * 128 + c] = m;
}

// ============================================================================
// GRU recurrence: 128 blocks = (dir, batch), no inter-block sync.
// 608 threads: lane pair (row, half) splits each gate row's 100-wide dot
// product.  half0: k floats [0,52)  = 26 u64 = 13 ulonglong2 (16B-aligned)
//             half1: k floats [52,100) = 24 u64 = 12 ulonglong2 (208B base,
//             16B-aligned).  Combined with one shfl_xor inside the lane pair.
// Weights register-resident packed f32x2; h broadcast via LDS.128.
// Time-max folded in; pool written transposed.
// ============================================================================
__global__ void __launch_bounds__(608) gru_kernel(
    const float* __restrict__ whh_f, const float* __restrict__ whh_b,
    const float* __restrict__ bhh_f, const float* __restrict__ bhh_b)
{
    const int blk = blockIdx.x;     // 0..127
    const int dir = blk >> 6;       // 0 fwd, 1 bwd
    const int b   = blk & 63;
    const int t   = threadIdx.x;    // 0..607
    const int row = t >> 1;         // gate row 0..303 (300 real)
    const int half = t & 1;         // k-range half
    const bool act = (row < 300);

    __shared__ __align__(16) float h_s[104];
    __shared__ float gh_s[300];
    __shared__ float gxn_s[100];

    const float* __restrict__ whh = dir ? whh_b : whh_f;
    const float* __restrict__ bhh = dir ? bhh_b : bhh_f;

    const int kbase = half ? 52 : 0;   // float offset of this half's k range
    u64 w2[26];                         // 26 u64 (half0) / 24 u64 (half1)
    #pragma unroll
    for (int k = 0; k < 26; k++) w2[k] = 0ull;
    if (act) {
        const u64* wrow = (const u64*)(whh + row * 100 + kbase); // 8B-aligned
        #pragma unroll
        for (int k = 0; k < 24; k++) w2[k] = wrow[k];
        if (!half) { w2[24] = wrow[24]; w2[25] = wrow[25]; }
    }
    float bh = (act && !half) ? bhh[row] : 0.f;

    if (t < 104) h_s[t] = 0.f;          // incl. 4 pad floats (safe LDS.128)
    float mx = -1e30f;

    // prefetch gx for first step (even thread of each pair)
    int s0 = dir ? 199 : 0;
    float gx_next = 0.f;
    if (act && !half) gx_next = g_gx[(size_t)(s0 * 64 + b) * 600 + dir * 300 + row];
    __syncthreads();

    #pragma unroll 1
    for (int sp = 0; sp < 200; sp++) {
        float gxv = gx_next;
        if (sp < 199 && act && !half) {
            int sn = dir ? (198 - sp) : (sp + 1);
            gx_next = g_gx[(size_t)(sn * 64 + b) * 600 + dir * 300 + row];
        }
        // ---- half dot product: 12-13 LDS.128 + 24-26 FMA2 ----
        u64 a0 = 0ull, a1 = 0ull;
        const ulonglong2* h4 = (const ulonglong2*)(h_s + kbase);
        #pragma unroll
        for (int q = 0; q < 12; q++) {
            ulonglong2 hv = h4[q];
            FMA2(a0, w2[2*q],   hv.x, a0);
            FMA2(a1, w2[2*q+1], hv.y, a1);
        }
        if (!half) {
            ulonglong2 hv = h4[12];     // floats 48..52
            FMA2(a0, w2[24], hv.x, a0);
            FMA2(a1, w2[25], hv.y, a1);
        }
        ADD2(a0, a0, a1);
        float2 f = unpack2(a0);
        float part = f.x + f.y;
        part += __shfl_xor_sync(0xFFFFFFFFu, part, 1);

        if (act && !half) {
            float acc = part + bh;
            if (row < 200) {
                float x = gxv + acc;                 // r,z rows
                gh_s[row] = 1.f / (1.f + __expf(-x));
            } else {
                gh_s[row] = acc;                     // raw hn
                gxn_s[row - 200] = gxv;
            }
        }
        __syncthreads();
        if (t < 100) {
            float r = gh_s[t];
            float z = gh_s[t + 100];
            float n = tanh_fast(gxn_s[t] + r * gh_s[t + 200]);
            float hn = fmaf(z, h_s[t] - n, n);       // (1-z)n + z h
            h_s[t] = hn;
            mx = fmaxf(mx, hn);
        }
        __syncthreads();
    }

    if (t < 100) g_poolT[(dir * 100 + t) * 64 + b] = mx;
}

// ============================================================================
// Final FC: out[b,o] = pool[b,:] . fc_w[o,:] + fc_b[o]
// ============================================================================
__global__ void __launch_bounds__(64) fc_kernel(
    const float* __restrict__ fcw, const float* __restrict__ fcb,
    float* __restrict__ out)
{
    const int o = blockIdx.x;   // 0..103
    const int b = threadIdx.x;  // 0..63
    __shared__ float w_s[200];
    for (int k = b; k < 200; k += 64) w_s[k] = fcw[o * 200 + k];
    __syncthreads();

    float acc = fcb[o];
    #pragma unroll
    for (int k = 0; k < 200; k++)
        acc = fmaf(w_s[k], g_poolT[k * 64 + b], acc);

    out[b * 104 + o] = acc;
}

// ============================================================================
extern "C" void kernel_launch(void* const* d_in, const int* in_sizes, int n_in,
                              void* d_out, int out_size)
{
    const int*   tokens = (const int*)  d_in[0];
    const float* emb    = (const float*)d_in[4];
    const float* w_lin  = (const float*)d_in[5];
    const float* b_lin  = (const float*)d_in[6];
    const float* w_ih_f = (const float*)d_in[7];
    const float* w_hh_f = (const float*)d_in[8];
    const float* b_ih_f = (const float*)d_in[9];
    const float* b_hh_f = (const float*)d_in[10];
    const float* w_ih_b = (const float*)d_in[11];
    const float* w_hh_b = (const float*)d_in[12];
    const float* b_ih_b = (const float*)d_in[13];
    const float* b_hh_b = (const float*)d_in[14];
    const float* fc_w   = (const float*)d_in[15];
    const float* fc_b   = (const float*)d_in[16];
    float* out = (float*)d_out;

    // K1: vocabulary-deduped linear: c_table[v] = emb[v] @ w_lin.T + b_lin
    {
        dim3 grid(2, (V_ + 127) / 128);
        gemm_nt_kernel<<<grid, 256>>>(emb, w_lin, w_lin, 128, 128,
                                      b_lin, b_lin, V_, 0);
    }
    // K2: gather + subtree sums + per-tree max pool
    tree_kernel<<<NT_, 128>>>(tokens);

    // K3: input gates for both GRU directions in one GEMM
    {
        dim3 grid(10, NT_ / 128);
        gemm_nt_kernel<<<grid, 256>>>(nullptr, w_ih_f, w_ih_b, 300, 600,
                                      b_ih_f, b_ih_b, NT_, 1);
    }
    // K4: serial recurrence, batch/dir parallel, fused time-max pool
    gru_kernel<<<128, 608>>>(w_hh_f, w_hh_b, b_hh_f, b_hh_b);

    // K5: final FC
    fc_kernel<<<104, 64>>>(fc_w, fc_b, out);
}

// round 5
// speedup vs baseline: 1.0307x; 1.0307x over previous
#include <cuda_runtime.h>
#include <math.h>

// ---- problem dims ----
#define B_   64
#define S_   200
#define T_   32
#define V_   50000
#define E_   128
#define C_   128
#define H_   100
#define OUT_ 104
#define NT_  (B_*S_)  // 12800 trees
#define N_   (NT_*T_) // 409600 nodes

// ---- packed f32x2 helpers (Blackwell FFMA2 path) ----
typedef unsigned long long u64;

#define FMA2(d, a, b, c) \
    asm("fma.rn.f32x2 %0, %1, %2, %3;" : "=l"(d) : "l"(a), "l"(b), "l"(c))
#define ADD2(d, a, b) \
    asm("add.rn.f32x2 %0, %1, %2;" : "=l"(d) : "l"(a), "l"(b))

__device__ __forceinline__ u64 dup2(float x) {
    u64 r;
    asm("mov.b64 %0, {%1, %1};" : "=l"(r) : "r"(__float_as_uint(x)));
    return r;
}
__device__ __forceinline__ float2 unpack2(u64 v) {
    unsigned lo, hi;
    asm("mov.b64 {%0, %1}, %2;" : "=r"(lo), "=r"(hi) : "l"(v));
    return make_float2(__uint_as_float(lo), __uint_as_float(hi));
}
// fast tanh via EX2/RCP MUFUs (accuracy ~1e-6, saturates at +/-1)
__device__ __forceinline__ float tanh_fast(float x) {
    return 1.0f - 2.0f * __frcp_rn(__expf(2.0f * x) + 1.0f);
}
__device__ __forceinline__ float sigmoid_fast(float x) {
    return __frcp_rn(1.0f + __expf(-x));
}

// ---- device scratch (no allocations allowed) ----
__device__ float g_ctable[V_ * C_];      // 25.6 MB : W*emb(v)+b per vocab entry
__device__ float g_treevec[NT_ * C_];    // 6.55 MB : per-tree max-pooled hidden
__device__ float g_gx[NT_ * 600];        // 30.7 MB : [s*64+b][600] input gates (f|b)
__device__ float g_poolT[200 * 64];      // [2H][B] : transposed time-max pool

// ============================================================================
// GEMM (NT): C[m,n] = sum_k A[m,k]*B[n,k] + bias[n].  K fixed at 128.
// BM=128, BN=64, BK=32, 256 threads, 8m x 4n per thread, f32x2-packed along m.
// ============================================================================
__global__ void __launch_bounds__(256) gemm_nt_kernel(
    const float* __restrict__ A_in,
    const float* __restrict__ B1, const float* __restrict__ B2, int nsplit,
    int Ncols,
    const float* __restrict__ bias1, const float* __restrict__ bias2,
    int M, int mode)
{
    __shared__ __align__(16) float As[32][132];   // k-major, 128 m cols
    __shared__ __align__(16) float Bs[32][68];    // k-major, 64 n cols

    const float* __restrict__ A = (mode == 0) ? A_in : g_treevec;

    const int m0 = blockIdx.y * 128;
    const int n0 = blockIdx.x * 64;
    const int tid = threadIdx.x;
    const int tx = tid & 15;       // n: 4 per thread
    const int ty = tid >> 4;       // m: 8 per thread

    u64 acc[4][4];                 // [m-pair][n]
    #pragma unroll
    for (int i = 0; i < 4; i++)
        #pragma unroll
        for (int j = 0; j < 4; j++) acc[i][j] = 0ull;

    for (int k0 = 0; k0 < 128; k0 += 32) {
        #pragma unroll
        for (int i = 0; i < 4; i++) {
            int f   = tid + i * 256;   // 0..1023 float4 slots
            int row = f >> 3;          // 0..127
            int kq  = f & 7;
            float4 v = make_float4(0.f, 0.f, 0.f, 0.f);
            int m = m0 + row;
            if (m < M) v = *(const float4*)(A + (size_t)m * 128 + k0 + kq * 4);
            As[kq*4+0][row] = v.x; As[kq*4+1][row] = v.y;
            As[kq*4+2][row] = v.z; As[kq*4+3][row] = v.w;
        }
        #pragma unroll
        for (int i = 0; i < 2; i++) {
            int f   = tid + i * 256;
            int row = f >> 3;          // 0..63
            int kq  = f & 7;
            float4 v = make_float4(0.f, 0.f, 0.f, 0.f);
            int n = n0 + row;
            if (n < Ncols) {
                const float* Bp = (n < nsplit) ? (B1 + (size_t)n * 128)
                                               : (B2 + (size_t)(n - nsplit) * 128);
                v = *(const float4*)(Bp + k0 + kq * 4);
            }
            Bs[kq*4+0][row] = v.x; Bs[kq*4+1][row] = v.y;
            Bs[kq*4+2][row] = v.z; Bs[kq*4+3][row] = v.w;
        }
        __syncthreads();

        #pragma unroll
        for (int kk = 0; kk < 32; kk++) {
            ulonglong2 ap0 = *(const ulonglong2*)&As[kk][ty * 8];
            ulonglong2 ap1 = *(const ulonglong2*)&As[kk][ty * 8 + 4];
            float4 bv = *(const float4*)&Bs[kk][tx * 4];
            u64 bd[4] = { dup2(bv.x), dup2(bv.y), dup2(bv.z), dup2(bv.w) };
            u64 ap[4] = { ap0.x, ap0.y, ap1.x, ap1.y };
            #pragma unroll
            for (int mp = 0; mp < 4; mp++)
                #pragma unroll
                for (int jj = 0; jj < 4; jj++)
                    FMA2(acc[mp][jj], ap[mp], bd[jj], acc[mp][jj]);
        }
        __syncthreads();
    }

    int nbase = n0 + tx * 4;
    bool nok = (nbase < Ncols);
    float4 bias4 = make_float4(0.f, 0.f, 0.f, 0.f);
    if (nok) {
        const float* bp = (nbase < nsplit) ? (bias1 + nbase)
                                           : (bias2 + (nbase - nsplit));
        bias4 = make_float4(bp[0], bp[1], bp[2], bp[3]);
    }
    #pragma unroll
    for (int mp = 0; mp < 4; mp++) {
        float2 c0 = unpack2(acc[mp][0]);
        float2 c1 = unpack2(acc[mp][1]);
        float2 c2 = unpack2(acc[mp][2]);
        float2 c3 = unpack2(acc[mp][3]);
        float4 rlo = make_float4(c0.x + bias4.x, c1.x + bias4.y,
                                 c2.x + bias4.z, c3.x + bias4.w);
        float4 rhi = make_float4(c0.y + bias4.x, c1.y + bias4.y,
                                 c2.y + bias4.z, c3.y + bias4.w);
        int m = m0 + ty * 8 + 2 * mp;
        #pragma unroll
        for (int half = 0; half < 2; half++) {
            int mm = m + half;
            if (mm >= M || !nok) continue;
            float4 r = half ? rhi : rlo;
            if (mode == 0) {
                *(float4*)(g_ctable + (size_t)mm * 128 + nbase) = r;
            } else {
                int s = mm % 200;     // tree mm = b*200 + s
                int b = mm / 200;
                *(float4*)(g_gx + (size_t)(s * 64 + b) * 600 + nbase) = r;
            }
        }
    }
}

// ============================================================================
// Tree encode: gather + fixed-topology subtree sums + max pool.
// ============================================================================
__global__ void __launch_bounds__(128) tree_kernel(const int* __restrict__ tokens)
{
    const int tree = blockIdx.x;
    const int c = threadIdx.x;
    __shared__ int tok[32];
    if (c < 32) tok[c] = tokens[tree * 32 + c];
    __syncthreads();

    float v[32];
    #pragma unroll
    for (int i = 0; i < 32; i++)
        v[i] = g_ctable[(size_t)tok[i] * 128 + c];

    #pragma unroll
    for (int i = 31; i >= 1; i--)
        v[(i - 1) >> 1] += v[i];

    float m = v[0];
    #pragma unroll
    for (int i = 1; i < 32; i++) m = fmaxf(m, v[i]);

    g_treevec[(size_t)tree * 128 + c] = m;
}

// ============================================================================
// GRU recurrence, gate-fused / single-barrier formulation.
// 128 blocks = (dir, batch). 224 threads = 112 lane pairs (j, half); j<100
// real. Each pair computes ALL THREE gate dot-products for hidden unit j,
// split across k: half0 = floats [0,52) (13 ull2), half1 = [52,100) (12 ull2).
// 3 shfl_xor(1) combine the halves; the EVEN thread applies sigmoid/tanh and
// updates h_j (held in its register + stored to the alternate smem buffer).
// ONE __syncthreads per step; h double-buffered so read(sp)/write(sp+1) can't
// race. gx (with b_hh folded at use) prefetched one step ahead.
// ============================================================================
__global__ void __launch_bounds__(224, 1) gru_kernel(
    const float* __restrict__ whh_f, const float* __restrict__ whh_b,
    const float* __restrict__ bhh_f, const float* __restrict__ bhh_b)
{
    const int blk  = blockIdx.x;    // 0..127
    const int dir  = blk >> 6;      // 0 fwd, 1 bwd
    const int b    = blk & 63;
    const int t    = threadIdx.x;   // 0..223
    const int j    = t >> 1;        // hidden unit 0..111 (100 real)
    const int half = t & 1;
    const bool act = (j < 100);
    const bool upd = act && (half == 0);

    __shared__ __align__(16) float hbuf[2][112];

    const float* __restrict__ whh = dir ? whh_b : whh_f;
    const float* __restrict__ bhh = dir ? bhh_b : bhh_f;

    const int kbase = half ? 52 : 0;    // float offset of this half's k range

    // weights: 3 gate rows (r=j, z=j+100, n=j+200), half-width each
    u64 wr[26], wz[26], wn[26];
    #pragma unroll
    for (int k = 0; k < 26; k++) { wr[k] = 0ull; wz[k] = 0ull; wn[k] = 0ull; }
    if (act) {
        const u64* rr = (const u64*)(whh + (j      ) * 100 + kbase);
        const u64* rz = (const u64*)(whh + (j + 100) * 100 + kbase);
        const u64* rn = (const u64*)(whh + (j + 200) * 100 + kbase);
        #pragma unroll
        for (int k = 0; k < 24; k++) { wr[k] = rr[k]; wz[k] = rz[k]; wn[k] = rn[k]; }
        if (!half) {
            wr[24] = rr[24]; wr[25] = rr[25];
            wz[24] = rz[24]; wz[25] = rz[25];
            wn[24] = rn[24]; wn[25] = rn[25];
        }
    }
    float bhr = 0.f, bhz = 0.f, bhn = 0.f;
    if (upd) { bhr = bhh[j]; bhz = bhh[j + 100]; bhn = bhh[j + 200]; }

    // zero both h buffers (pads included -> no NaN leaks through zero weights)
    if (t < 112) { hbuf[0][t] = 0.f; hbuf[1][t] = 0.f; }

    float h_old = 0.f;       // even thread's register copy of h_j
    float mx = -1e30f;

    // prefetch gx for step 0 (even threads), bias folded
    float gxr = 0.f, gxz = 0.f, gxn = 0.f;
    if (upd) {
        int s0 = dir ? 199 : 0;
        const float* gp = g_gx + (size_t)(s0 * 64 + b) * 600 + dir * 300;
        gxr = gp[j] + bhr; gxz = gp[j + 100] + bhz; gxn = gp[j + 200] + bhn;
    }
    __syncthreads();

    #pragma unroll 1
    for (int sp = 0; sp < 200; sp++) {
        const int cur = sp & 1;
        float gr = gxr, gz = gxz, gn = gxn;
        // prefetch next step's gx (off critical path)
        if (sp < 199 && upd) {
            int sn = dir ? (198 - sp) : (sp + 1);
            const float* gp = g_gx + (size_t)(sn * 64 + b) * 600 + dir * 300;
            gxr = gp[j] + bhr; gxz = gp[j + 100] + bhz; gxn = gp[j + 200] + bhn;
        }

        // ---- 3 half dot-products: 12-13 LDS.128, 72-78 FMA2, 6 accums ----
        u64 ar0 = 0ull, ar1 = 0ull, az0 = 0ull, az1 = 0ull, an0 = 0ull, an1 = 0ull;
        const ulonglong2* h4 = (const ulonglong2*)(&hbuf[cur][0] + kbase);
        #pragma unroll
        for (int q = 0; q < 12; q++) {
            ulonglong2 hv = h4[q];
            FMA2(ar0, wr[2*q],   hv.x, ar0);
            FMA2(ar1, wr[2*q+1], hv.y, ar1);
            FMA2(az0, wz[2*q],   hv.x, az0);
            FMA2(az1, wz[2*q+1], hv.y, az1);
            FMA2(an0, wn[2*q],   hv.x, an0);
            FMA2(an1, wn[2*q+1], hv.y, an1);
        }
        if (!half) {
            ulonglong2 hv = h4[12];     // floats 48..52
            FMA2(ar0, wr[24], hv.x, ar0);
            FMA2(ar1, wr[25], hv.y, ar1);
            FMA2(az0, wz[24], hv.x, az0);
            FMA2(az1, wz[25], hv.y, az1);
            FMA2(an0, wn[24], hv.x, an0);
            FMA2(an1, wn[25], hv.y, an1);
        }
        ADD2(ar0, ar0, ar1);
        ADD2(az0, az0, az1);
        ADD2(an0, an0, an1);
        float2 fr = unpack2(ar0);
        float2 fz = unpack2(az0);
        float2 fn = unpack2(an0);
        float sr = fr.x + fr.y;
        float sz = fz.x + fz.y;
        float sn = fn.x + fn.y;
        sr += __shfl_xor_sync(0xFFFFFFFFu, sr, 1);
        sz += __shfl_xor_sync(0xFFFFFFFFu, sz, 1);
        sn += __shfl_xor_sync(0xFFFFFFFFu, sn, 1);

        if (upd) {
            float r = sigmoid_fast(gr + sr);
            float z = sigmoid_fast(gz + sz);
            float n = tanh_fast(gn + fmaf(r, sn, 0.f));
            float hn = fmaf(z, h_old - n, n);        // (1-z)n + z h
            h_old = hn;
            mx = fmaxf(mx, hn);
            hbuf[cur ^ 1][j] = hn;
        }
        __syncthreads();
    }

    if (upd) g_poolT[(dir * 100 + j) * 64 + b] = mx;
}

// ============================================================================
// Final FC: out[b,o] = pool[b,:] . fc_w[o,:] + fc_b[o]
// ============================================================================
__global__ void __launch_bounds__(64) fc_kernel(
    const float* __restrict__ fcw, const float* __restrict__ fcb,
    float* __restrict__ out)
{
    const int o = blockIdx.x;   // 0..103
    const int b = threadIdx.x;  // 0..63
    __shared__ float w_s[200];
    for (int k = b; k < 200; k += 64) w_s[k] = fcw[o * 200 + k];
    __syncthreads();

    float acc = fcb[o];
    #pragma unroll
    for (int k = 0; k < 200; k++)
        acc = fmaf(w_s[k], g_poolT[k * 64 + b], acc);

    out[b * 104 + o] = acc;
}

// ============================================================================
extern "C" void kernel_launch(void* const* d_in, const int* in_sizes, int n_in,
                              void* d_out, int out_size)
{
    const int*   tokens = (const int*)  d_in[0];
    const float* emb    = (const float*)d_in[4];
    const float* w_lin  = (const float*)d_in[5];
    const float* b_lin  = (const float*)d_in[6];
    const float* w_ih_f = (const float*)d_in[7];
    const float* w_hh_f = (const float*)d_in[8];
    const float* b_ih_f = (const float*)d_in[9];
    const float* b_hh_f = (const float*)d_in[10];
    const float* w_ih_b = (const float*)d_in[11];
    const float* w_hh_b = (const float*)d_in[12];
    const float* b_ih_b = (const float*)d_in[13];
    const float* b_hh_b = (const float*)d_in[14];
    const float* fc_w   = (const float*)d_in[15];
    const float* fc_b   = (const float*)d_in[16];
    float* out = (float*)d_out;

    // K1: vocabulary-deduped linear: c_table[v] = emb[v] @ w_lin.T + b_lin
    {
        dim3 grid(2, (V_ + 127) / 128);
        gemm_nt_kernel<<<grid, 256>>>(emb, w_lin, w_lin, 128, 128,
                                      b_lin, b_lin, V_, 0);
    }
    // K2: gather + subtree sums + per-tree max pool
    tree_kernel<<<NT_, 128>>>(tokens);

    // K3: input gates for both GRU directions in one GEMM
    {
        dim3 grid(10, NT_ / 128);
        gemm_nt_kernel<<<grid, 256>>>(nullptr, w_ih_f, w_ih_b, 300, 600,
                                      b_ih_f, b_ih_b, NT_, 1);
    }
    // K4: serial recurrence, gate-fused, single barrier per step
    gru_kernel<<<128, 224>>>(w_hh_f, w_hh_b, b_hh_f, b_hh_b);

    // K5: final FC
    fc_kernel<<<104, 64>>>(fc_w, fc_b, out);
}

// round 7
// speedup vs baseline: 1.0460x; 1.0149x over previous
#include <cuda_runtime.h>
#include <math.h>

// ---- problem dims ----
#define B_   64
#define S_   200
#define T_   32
#define V_   50000
#define E_   128
#define C_   128
#define H_   100
#define OUT_ 104
#define NT_  (B_*S_)  // 12800 trees
#define N_   (NT_*T_) // 409600 nodes

// ---- packed f32x2 helpers (Blackwell FFMA2 path) ----
typedef unsigned long long u64;

#define FMA2(d, a, b, c) \
    asm("fma.rn.f32x2 %0, %1, %2, %3;" : "=l"(d) : "l"(a), "l"(b), "l"(c))
#define ADD2(d, a, b) \
    asm("add.rn.f32x2 %0, %1, %2;" : "=l"(d) : "l"(a), "l"(b))

__device__ __forceinline__ u64 dup2(float x) {
    u64 r;
    asm("mov.b64 %0, {%1, %1};" : "=l"(r) : "r"(__float_as_uint(x)));
    return r;
}
__device__ __forceinline__ float2 unpack2(u64 v) {
    unsigned lo, hi;
    asm("mov.b64 {%0, %1}, %2;" : "=r"(lo), "=r"(hi) : "l"(v));
    return make_float2(__uint_as_float(lo), __uint_as_float(hi));
}
// fast tanh / sigmoid via EX2/RCP MUFUs (accuracy ~1e-6)
__device__ __forceinline__ float tanh_fast(float x) {
    return 1.0f - 2.0f * __frcp_rn(__expf(2.0f * x) + 1.0f);
}
__device__ __forceinline__ float sigmoid_fast(float x) {
    return __frcp_rn(1.0f + __expf(-x));
}

// ---- device scratch (no allocations allowed) ----
__device__ float g_ctable[V_ * C_];      // 25.6 MB : W*emb(v)+b per vocab entry
__device__ float g_treevec[NT_ * C_];    // 6.55 MB : per-tree max-pooled hidden
__device__ float g_gx[NT_ * 600];        // 30.7 MB : [s*64+b][600] input gates (f|b)
__device__ float g_poolT[200 * 64];      // [2H][B] : transposed time-max pool

// ============================================================================
// GEMM (NT): C[m,n] = sum_k A[m,k]*B[n,k] + bias[n].  K fixed at 128.
// BM=128, BN=64, BK=32, 256 threads, 8m x 4n per thread, f32x2-packed along m.
// ============================================================================
__global__ void __launch_bounds__(256) gemm_nt_kernel(
    const float* __restrict__ A_in,
    const float* __restrict__ B1, const float* __restrict__ B2, int nsplit,
    int Ncols,
    const float* __restrict__ bias1, const float* __restrict__ bias2,
    int M, int mode)
{
    __shared__ __align__(16) float As[32][132];   // k-major, 128 m cols
    __shared__ __align__(16) float Bs[32][68];    // k-major, 64 n cols

    const float* __restrict__ A = (mode == 0) ? A_in : g_treevec;

    const int m0 = blockIdx.y * 128;
    const int n0 = blockIdx.x * 64;
    const int tid = threadIdx.x;
    const int tx = tid & 15;       // n: 4 per thread
    const int ty = tid >> 4;       // m: 8 per thread

    u64 acc[4][4];                 // [m-pair][n]
    #pragma unroll
    for (int i = 0; i < 4; i++)
        #pragma unroll
        for (int j = 0; j < 4; j++) acc[i][j] = 0ull;

    for (int k0 = 0; k0 < 128; k0 += 32) {
        #pragma unroll
        for (int i = 0; i < 4; i++) {
            int f   = tid + i * 256;   // 0..1023 float4 slots
            int row = f >> 3;          // 0..127
            int kq  = f & 7;
            float4 v = make_float4(0.f, 0.f, 0.f, 0.f);
            int m = m0 + row;
            if (m < M) v = *(const float4*)(A + (size_t)m * 128 + k0 + kq * 4);
            As[kq*4+0][row] = v.x; As[kq*4+1][row] = v.y;
            As[kq*4+2][row] = v.z; As[kq*4+3][row] = v.w;
        }
        #pragma unroll
        for (int i = 0; i < 2; i++) {
            int f   = tid + i * 256;
            int row = f >> 3;          // 0..63
            int kq  = f & 7;
            float4 v = make_float4(0.f, 0.f, 0.f, 0.f);
            int n = n0 + row;
            if (n < Ncols) {
                const float* Bp = (n < nsplit) ? (B1 + (size_t)n * 128)
                                               : (B2 + (size_t)(n - nsplit) * 128);
                v = *(const float4*)(Bp + k0 + kq * 4);
            }
            Bs[kq*4+0][row] = v.x; Bs[kq*4+1][row] = v.y;
            Bs[kq*4+2][row] = v.z; Bs[kq*4+3][row] = v.w;
        }
        __syncthreads();

        #pragma unroll
        for (int kk = 0; kk < 32; kk++) {
            ulonglong2 ap0 = *(const ulonglong2*)&As[kk][ty * 8];
            ulonglong2 ap1 = *(const ulonglong2*)&As[kk][ty * 8 + 4];
            float4 bv = *(const float4*)&Bs[kk][tx * 4];
            u64 bd[4] = { dup2(bv.x), dup2(bv.y), dup2(bv.z), dup2(bv.w) };
            u64 ap[4] = { ap0.x, ap0.y, ap1.x, ap1.y };
            #pragma unroll
            for (int mp = 0; mp < 4; mp++)
                #pragma unroll
                for (int jj = 0; jj < 4; jj++)
                    FMA2(acc[mp][jj], ap[mp], bd[jj], acc[mp][jj]);
        }
        __syncthreads();
    }

    int nbase = n0 + tx * 4;
    bool nok = (nbase < Ncols);
    float4 bias4 = make_float4(0.f, 0.f, 0.f, 0.f);
    if (nok) {
        const float* bp = (nbase < nsplit) ? (bias1 + nbase)
                                           : (bias2 + (nbase - nsplit));
        bias4 = make_float4(bp[0], bp[1], bp[2], bp[3]);
    }
    #pragma unroll
    for (int mp = 0; mp < 4; mp++) {
        float2 c0 = unpack2(acc[mp][0]);
        float2 c1 = unpack2(acc[mp][1]);
        float2 c2 = unpack2(acc[mp][2]);
        float2 c3 = unpack2(acc[mp][3]);
        float4 rlo = make_float4(c0.x + bias4.x, c1.x + bias4.y,
                                 c2.x + bias4.z, c3.x + bias4.w);
        float4 rhi = make_float4(c0.y + bias4.x, c1.y + bias4.y,
                                 c2.y + bias4.z, c3.y + bias4.w);
        int m = m0 + ty * 8 + 2 * mp;
        #pragma unroll
        for (int half = 0; half < 2; half++) {
            int mm = m + half;
            if (mm >= M || !nok) continue;
            float4 r = half ? rhi : rlo;
            if (mode == 0) {
                *(float4*)(g_ctable + (size_t)mm * 128 + nbase) = r;
            } else {
                int s = mm % 200;     // tree mm = b*200 + s
                int b = mm / 200;
                *(float4*)(g_gx + (size_t)(s * 64 + b) * 600 + nbase) = r;
            }
        }
    }
}

// ============================================================================
// Tree encode: gather + fixed-topology subtree sums + max pool.
// ============================================================================
__global__ void __launch_bounds__(128) tree_kernel(const int* __restrict__ tokens)
{
    const int tree = blockIdx.x;
    const int c = threadIdx.x;
    __shared__ int tok[32];
    if (c < 32) tok[c] = tokens[tree * 32 + c];
    __syncthreads();

    float v[32];
    #pragma unroll
    for (int i = 0; i < 32; i++)
        v[i] = g_ctable[(size_t)tok[i] * 128 + c];

    #pragma unroll
    for (int i = 31; i >= 1; i--)
        v[(i - 1) >> 1] += v[i];

    float m = v[0];
    #pragma unroll
    for (int i = 1; i < 32; i++) m = fmaxf(m, v[i]);

    g_treevec[(size_t)tree * 128 + c] = m;
}

// ============================================================================
// GRU recurrence — 6-lane-unit, single-barrier formulation.
// 128 blocks = (dir, batch). 640 threads = 20 warps; each warp owns 5 hidden
// units x 6 lanes (lanes 30,31 idle). Lane role within unit: (gate g, k-half).
//   half0 = k floats [0,52)  = 26 u64;  half1 = [52,100) = 24 u64.
// Each lane: 24-26 FMA2 over its weight slice (~52 regs -> loads batchable).
// shfl_xor(1) combines k-halves; leader (role 0) gathers z,n sums via 2 shfl,
// applies sigmoid/tanh (MUFU), updates h_j. ONE __syncthreads per step with
// h double-buffered in smem. gx prefetched one step ahead; b_hh folded into
// the h-side sums (n-gate keeps xn separate: n = tanh(xn + r*(h.wn + bhn))).
// ============================================================================
__global__ void __launch_bounds__(640, 1) gru_kernel(
    const float* __restrict__ whh_f, const float* __restrict__ whh_b,
    const float* __restrict__ bhh_f, const float* __restrict__ bhh_b)
{
    const int blk  = blockIdx.x;    // 0..127
    const int dir  = blk >> 6;      // 0 fwd, 1 bwd
    const int b    = blk & 63;
    const int t    = threadIdx.x;   // 0..639
    const int w    = t >> 5;
    const int l    = t & 31;
    const int unit = l / 6;         // 0..5 (5 = idle lanes 30,31)
    const int role = l % 6;
    const int g    = role >> 1;     // 0=r, 1=z, 2=n
    const int half = role & 1;
    const int j    = w * 5 + unit;  // hidden unit (valid when act)
    const bool act   = (l < 30);
    const bool lead  = act && (role == 0);
    const bool evenh = (half == 0);

    __shared__ __align__(16) float hbuf[2][112];

    const float* __restrict__ whh = dir ? whh_b : whh_f;
    const float* __restrict__ bhh = dir ? bhh_b : bhh_f;

    const int row   = g * 100 + j;      // gate row in [0,300) when act
    const int kbase = half ? 52 : 0;

    // ---- weights: one gate row, one k-half ----
    u64 w2[26];
    #pragma unroll
    for (int k = 0; k < 26; k++) w2[k] = 0ull;
    if (act) {
        const u64* wr = (const u64*)(whh + row * 100 + kbase);  // 8B aligned
        #pragma unroll
        for (int k = 0; k < 24; k++) w2[k] = wr[k];
        if (!half) { w2[24] = wr[24]; w2[25] = wr[25]; }
    }
    // b_hh folded into even-half partial (n-gate: bias only, xn kept separate)
    float bias = (act && evenh) ? bhh[row] : 0.f;

    if (t < 112) { hbuf[0][t] = 0.f; hbuf[1][t] = 0.f; }

    float h_old = 0.f, mx = -1e30f;

    // ---- gx prefetch for step 0 ----
    // roles 0,2 (r,z even-half) load their gate's gx; leader also loads xn.
    int s0 = dir ? 199 : 0;
    float gxv = 0.f, gxn_l = 0.f;
    {
        const float* gp = g_gx + (size_t)(s0 * 64 + b) * 600 + dir * 300;
        if (act && evenh && g < 2) gxv = gp[row];
        if (lead) gxn_l = gp[200 + j];
    }
    __syncthreads();

    #pragma unroll 1
    for (int sp = 0; sp < 200; sp++) {
        const int cur = sp & 1;
        float cgx = gxv, cxn = gxn_l;
        // prefetch next step's gx (off critical path)
        if (sp < 199) {
            int sn = dir ? (198 - sp) : (sp + 1);
            const float* gp = g_gx + (size_t)(sn * 64 + b) * 600 + dir * 300;
            if (act && evenh && g < 2) gxv = gp[row];
            if (lead) gxn_l = gp[200 + j];
        }

        // ---- half-width dot product: 12-13 LDS.128 + 24-26 FMA2 ----
        u64 a0 = 0ull, a1 = 0ull;
        const ulonglong2* h4 = (const ulonglong2*)(&hbuf[cur][0] + kbase);
        #pragma unroll
        for (int q = 0; q < 12; q++) {
            ulonglong2 hv = h4[q];
            FMA2(a0, w2[2*q],   hv.x, a0);
            FMA2(a1, w2[2*q+1], hv.y, a1);
        }
        if (!half) {
            ulonglong2 hv = h4[12];     // floats 48..52
            FMA2(a0, w2[24], hv.x, a0);
            FMA2(a1, w2[25], hv.y, a1);
        }
        ADD2(a0, a0, a1);
        float2 f = unpack2(a0);
        float part = f.x + f.y + bias + cgx;   // bias/cgx are 0 where N/A
        part += __shfl_xor_sync(0xFFFFFFFFu, part, 1);

        // gather z and n sums to the unit leader (all lanes execute shfl)
        int ubase = l - role;
        float zsum = __shfl_sync(0xFFFFFFFFu, part, ubase + 2);
        float nsum = __shfl_sync(0xFFFFFFFFu, part, ubase + 4);

        if (lead) {
            float r  = sigmoid_fast(part);          // xr + h.wr + br (+bihr)
            float z  = sigmoid_fast(zsum);
            float n  = tanh_fast(cxn + r * nsum);   // xn + r*(h.wn + bn)
            float hn = n + z * (h_old - n);
            h_old = hn;
            mx = fmaxf(mx, hn);
            hbuf[cur ^ 1][j] = hn;
        }
        __syncthreads();
    }

    if (lead) g_poolT[(dir * 100 + j) * 64 + b] = mx;
}

// ============================================================================
// Final FC: out[b,o] = pool[b,:] . fc_w[o,:] + fc_b[o]
// ============================================================================
__global__ void __launch_bounds__(64) fc_kernel(
    const float* __restrict__ fcw, const float* __restrict__ fcb,
    float* __restrict__ out)
{
    const int o = blockIdx.x;   // 0..103
    const int b = threadIdx.x;  // 0..63
    __shared__ float w_s[200];
    for (int k = b; k < 200; k += 64) w_s[k] = fcw[o * 200 + k];
    __syncthreads();

    float acc = fcb[o];
    #pragma unroll
    for (int k = 0; k < 200; k++)
        acc = fmaf(w_s[k], g_poolT[k * 64 + b], acc);

    out[b * 104 + o] = acc;
}

// ============================================================================
extern "C" void kernel_launch(void* const* d_in, const int* in_sizes, int n_in,
                              void* d_out, int out_size)
{
    const int*   tokens = (const int*)  d_in[0];
    const float* emb    = (const float*)d_in[4];
    const float* w_lin  = (const float*)d_in[5];
    const float* b_lin  = (const float*)d_in[6];
    const float* w_ih_f = (const float*)d_in[7];
    const float* w_hh_f = (const float*)d_in[8];
    const float* b_ih_f = (const float*)d_in[9];
    const float* b_hh_f = (const float*)d_in[10];
    const float* w_ih_b = (const float*)d_in[11];
    const float* w_hh_b = (const float*)d_in[12];
    const float* b_ih_b = (const float*)d_in[13];
    const float* b_hh_b = (const float*)d_in[14];
    const float* fc_w   = (const float*)d_in[15];
    const float* fc_b   = (const float*)d_in[16];
    float* out = (float*)d_out;

    // K1: vocabulary-deduped linear: c_table[v] = emb[v] @ w_lin.T + b_lin
    {
        dim3 grid(2, (V_ + 127) / 128);
        gemm_nt_kernel<<<grid, 256>>>(emb, w_lin, w_lin, 128, 128,
                                      b_lin, b_lin, V_, 0);
    }
    // K2: gather + subtree sums + per-tree max pool
    tree_kernel<<<NT_, 128>>>(tokens);

    // K3: input gates for both GRU directions in one GEMM
    {
        dim3 grid(10, NT_ / 128);
        gemm_nt_kernel<<<grid, 256>>>(nullptr, w_ih_f, w_ih_b, 300, 600,
                                      b_ih_f, b_ih_b, NT_, 1);
    }
    // K4: serial recurrence, 6-lane units, single barrier per step
    gru_kernel<<<128, 640>>>(w_hh_f, w_hh_b, b_hh_f, b_hh_b);

    // K5: final FC
    fc_kernel<<<104, 64>>>(fc_w, fc_b, out);
}